// round 5
// baseline (speedup 1.0000x reference)
#include <cuda_runtime.h>

#define N_NODES 100000
#define F_IN    128
#define HDIM    64
#define CDIM    40

// ---- scratch (device globals: no allocation allowed) ----
__device__ __align__(256) int   g_cnt [N_NODES];
__device__ __align__(256) float g_dinv[N_NODES];
__device__ __align__(256) float g_h1s [N_NODES * HDIM];   // x@W1 (unscaled)
__device__ __align__(256) float g_agg1[N_NODES * HDIM];   // init=dinv*h1 (self), += dinv[s]*h1[s]
__device__ __align__(256) float g_h2s [N_NODES * CDIM];   // pre-scaled by dinv[row]
__device__ __align__(256) float g_agg2[N_NODES * CDIM];

// ---------------------------------------------------------------- degree ----
__global__ void k_zero() {
    int i = blockIdx.x * blockDim.x + threadIdx.x;
    if (i < N_NODES) g_cnt[i] = 0;
}

__global__ void k_count(const int* __restrict__ ei, int E) {
    int e = blockIdx.x * blockDim.x + threadIdx.x;
    if (e >= E) return;
    int d = ei[E + e];
    if ((unsigned)d < (unsigned)N_NODES) atomicAdd(&g_cnt[d], 1);
}

// ------------------------------------------------ GEMM1: h1s = x@W1 (unscaled)
// block 256 thr, tile 128 rows x 64 cols; thread: 8 rows x 4 cols, k-step 2
#define XPAD 36
__global__ __launch_bounds__(256, 3) void k_gemm1(const float* __restrict__ x,
                                                  const float* __restrict__ W1) {
    __shared__ float Ws[32 * 64];         // 8 KB
    __shared__ float Xs[128 * XPAD];      // 18.4 KB

    const int tid = threadIdx.x;
    const int cg  = tid & 15;             // cols cg*4 .. cg*4+3
    const int rg  = tid >> 4;             // rows rg*8 .. rg*8+7
    const int rowBase = blockIdx.x * 128;

    float4 acc[8];
    #pragma unroll
    for (int r = 0; r < 8; r++) acc[r] = make_float4(0.f, 0.f, 0.f, 0.f);

    for (int k0 = 0; k0 < F_IN; k0 += 32) {
        {   // stage W chunk [32][64]: 8 floats per thread
            int r = tid >> 3, c = (tid & 7) * 8;
            float4 a = *(const float4*)&W1[(k0 + r) * HDIM + c];
            float4 b = *(const float4*)&W1[(k0 + r) * HDIM + c + 4];
            *(float4*)&Ws[r * 64 + c]     = a;
            *(float4*)&Ws[r * 64 + c + 4] = b;
        }
        {   // stage X chunk [128][32] into padded rows: 16 floats per thread
            int r = tid >> 1, kk = (tid & 1) * 16;
            int row = rowBase + r;
            float* s = &Xs[r * XPAD + kk];
            if (row < N_NODES) {
                const float* xp = &x[(long long)row * F_IN + k0 + kk];
                float4 a = *(const float4*)(xp);
                float4 b = *(const float4*)(xp + 4);
                float4 c = *(const float4*)(xp + 8);
                float4 d = *(const float4*)(xp + 12);
                *(float4*)(s)      = a;
                *(float4*)(s + 4)  = b;
                *(float4*)(s + 8)  = c;
                *(float4*)(s + 12) = d;
            } else {
                *(float4*)(s)      = make_float4(0.f,0.f,0.f,0.f);
                *(float4*)(s + 4)  = make_float4(0.f,0.f,0.f,0.f);
                *(float4*)(s + 8)  = make_float4(0.f,0.f,0.f,0.f);
                *(float4*)(s + 12) = make_float4(0.f,0.f,0.f,0.f);
            }
        }
        __syncthreads();
        #pragma unroll
        for (int k = 0; k < 32; k += 2) {
            float4 w0 = *(const float4*)&Ws[k * 64 + cg * 4];
            float4 w1 = *(const float4*)&Ws[(k + 1) * 64 + cg * 4];
            #pragma unroll
            for (int r = 0; r < 8; r++) {
                float2 xv = *(const float2*)&Xs[(rg * 8 + r) * XPAD + k];
                acc[r].x += xv.x * w0.x; acc[r].y += xv.x * w0.y;
                acc[r].z += xv.x * w0.z; acc[r].w += xv.x * w0.w;
                acc[r].x += xv.y * w1.x; acc[r].y += xv.y * w1.y;
                acc[r].z += xv.y * w1.z; acc[r].w += xv.y * w1.w;
            }
        }
        __syncthreads();
    }

    #pragma unroll
    for (int r = 0; r < 8; r++) {
        int row = rowBase + rg * 8 + r;
        if (row < N_NODES)
            *(float4*)&g_h1s[(long long)row * HDIM + cg * 4] = acc[r];
    }
}

// ------------------- init1: dinv = rsqrt(1+cnt); agg1 = dinv[row]*h1s (self) ----
__global__ void k_init1() {
    int idx = blockIdx.x * blockDim.x + threadIdx.x;    // one per float4
    if (idx >= N_NODES * (HDIM / 4)) return;
    int row = idx >> 4;
    float d = rsqrtf(1.0f + (float)g_cnt[row]);
    if ((idx & 15) == 0) g_dinv[row] = d;
    float4 v = *(const float4*)&g_h1s[(long long)idx * 4];
    v.x *= d; v.y *= d; v.z *= d; v.w *= d;
    *(float4*)&g_agg1[(long long)idx * 4] = v;
}

// ----------------------------------- scatter1: agg1[dst] += dinv[s]*h1s[src] ----
__global__ void k_scatter1(const int* __restrict__ ei, int E) {
    long long idx = (long long)blockIdx.x * blockDim.x + threadIdx.x;
    long long total = (long long)E * 16;          // 16 float4 chunks per edge
    if (idx >= total) return;
    int e = (int)(idx >> 4);
    int c = ((int)idx & 15) * 4;
    int s = ei[e], d = ei[E + e];
    if ((unsigned)s >= (unsigned)N_NODES || (unsigned)d >= (unsigned)N_NODES) return;
    float ds = g_dinv[s];
    float4 v = *(const float4*)&g_h1s[(long long)s * HDIM + c];
    v.x *= ds; v.y *= ds; v.z *= ds; v.w *= ds;
    float* p = &g_agg1[(long long)d * HDIM + c];
    asm volatile("red.global.add.v4.f32 [%0], {%1, %2, %3, %4};"
                 :: "l"(p), "f"(v.x), "f"(v.y), "f"(v.z), "f"(v.w) : "memory");
}

// --------------------------- GEMM2: h2s = relu(dinv*agg1 + b1) @ W2 * dinv ----
__global__ __launch_bounds__(320) void k_gemm2(const float* __restrict__ W2,
                                               const float* __restrict__ b1) {
    __shared__ float Ws[64 * 40];
    __shared__ float Xs[128 * 65];
    __shared__ float Bs[64];

    const int tid = threadIdx.x;
    const int cg  = tid % 10;            // cols cg*4 .. cg*4+3
    const int rg  = tid / 10;            // rows rg*4 .. rg*4+3
    const int rowBase = blockIdx.x * 128;

    for (int i = tid; i < 64 * 40; i += 320) Ws[i] = W2[i];
    if (tid < 64) Bs[tid] = b1[tid];
    __syncthreads();

    for (int i = tid; i < 128 * 64; i += 320) {
        int r = i >> 6, k = i & 63;
        int row = rowBase + r;
        float v = 0.f;
        if (row < N_NODES)
            v = fmaxf(g_dinv[row] * g_agg1[(long long)row * HDIM + k] + Bs[k], 0.f);
        Xs[r * 65 + k] = v;
    }
    __syncthreads();

    float4 acc[4];
    #pragma unroll
    for (int r = 0; r < 4; r++) acc[r] = make_float4(0.f, 0.f, 0.f, 0.f);

    #pragma unroll 4
    for (int k = 0; k < 64; k++) {
        float4 w = *(const float4*)&Ws[k * 40 + cg * 4];
        #pragma unroll
        for (int r = 0; r < 4; r++) {
            float xv = Xs[(rg * 4 + r) * 65 + k];
            acc[r].x += xv * w.x; acc[r].y += xv * w.y;
            acc[r].z += xv * w.z; acc[r].w += xv * w.w;
        }
    }

    #pragma unroll
    for (int r = 0; r < 4; r++) {
        int row = rowBase + rg * 4 + r;
        if (row < N_NODES) {
            float s = g_dinv[row];
            float4 o = make_float4(acc[r].x * s, acc[r].y * s,
                                   acc[r].z * s, acc[r].w * s);
            *(float4*)&g_h2s [(long long)row * CDIM + cg * 4] = o;
            *(float4*)&g_agg2[(long long)row * CDIM + cg * 4] = o;  // self-loop init
        }
    }
}

// ------------------------------------------------ scatter2: agg2[dst] += h2s[src]
__global__ void k_scatter2(const int* __restrict__ ei, int E) {
    long long idx = (long long)blockIdx.x * blockDim.x + threadIdx.x;
    long long total = (long long)E * 10;          // 10 float4 chunks per edge
    if (idx >= total) return;
    int e = (int)(idx / 10);
    int c = (int)(idx % 10) * 4;
    int s = ei[e], d = ei[E + e];
    if ((unsigned)s >= (unsigned)N_NODES || (unsigned)d >= (unsigned)N_NODES) return;
    float4 v = *(const float4*)&g_h2s[(long long)s * CDIM + c];
    float* p = &g_agg2[(long long)d * CDIM + c];
    asm volatile("red.global.add.v4.f32 [%0], {%1, %2, %3, %4};"
                 :: "l"(p), "f"(v.x), "f"(v.y), "f"(v.z), "f"(v.w) : "memory");
}

// -------------------------------------- final: out = log_softmax(dinv*agg2 + b2)
__global__ void k_final(const float* __restrict__ b2, float* __restrict__ out) {
    int gtid = blockIdx.x * blockDim.x + threadIdx.x;
    int row  = gtid >> 5;
    int lane = threadIdx.x & 31;
    if (row >= N_NODES) return;
    const float* rp = &g_agg2[(long long)row * CDIM];
    float s  = g_dinv[row];
    float a0 = s * rp[lane] + b2[lane];
    float a1 = (lane < 8) ? (s * rp[32 + lane] + b2[32 + lane]) : -3.4e38f;
    float m  = fmaxf(a0, a1);
    #pragma unroll
    for (int o = 16; o; o >>= 1) m = fmaxf(m, __shfl_xor_sync(0xFFFFFFFFu, m, o));
    float es = expf(a0 - m) + ((lane < 8) ? expf(a1 - m) : 0.f);
    #pragma unroll
    for (int o = 16; o; o >>= 1) es += __shfl_xor_sync(0xFFFFFFFFu, es, o);
    float l = m + logf(es);
    out[(long long)row * CDIM + lane] = a0 - l;
    if (lane < 8) out[(long long)row * CDIM + 32 + lane] = a1 - l;
}

// ---------------------------------------------------------------------------
extern "C" void kernel_launch(void* const* d_in, const int* in_sizes, int n_in,
                              void* d_out, int out_size) {
    const float* x  = (const float*)d_in[0];
    const int*   ei = (const int*)  d_in[1];
    const float* W1 = (const float*)d_in[2];
    const float* b1 = (const float*)d_in[3];
    const float* W2 = (const float*)d_in[4];
    const float* b2 = (const float*)d_in[5];
    float* out = (float*)d_out;
    const int E = in_sizes[1] / 2;

    // one-time side-stream resources (no device memory involved)
    static cudaStream_t s_b = nullptr;
    static cudaEvent_t  ev_fork = nullptr, ev_join = nullptr;
    if (s_b == nullptr) {
        cudaStreamCreateWithFlags(&s_b, cudaStreamNonBlocking);
        cudaEventCreateWithFlags(&ev_fork, cudaEventDisableTiming);
        cudaEventCreateWithFlags(&ev_join, cudaEventDisableTiming);
    }

    // detect which default-stream alias is being captured (if any)
    cudaStream_t main_s = nullptr;
    cudaStreamCaptureStatus st = cudaStreamCaptureStatusNone;
    if (cudaStreamIsCapturing(cudaStreamPerThread, &st) == cudaSuccess &&
        st == cudaStreamCaptureStatusActive) {
        main_s = cudaStreamPerThread;
    } else {
        st = cudaStreamCaptureStatusNone;
        if (cudaStreamIsCapturing(cudaStreamLegacy, &st) == cudaSuccess &&
            st == cudaStreamCaptureStatusActive)
            main_s = cudaStreamLegacy;
    }

    if (main_s != nullptr) {
        // fork: degree chain on s_b, gemm1 on main, join before init1
        cudaEventRecord(ev_fork, main_s);
        cudaStreamWaitEvent(s_b, ev_fork, 0);
        k_zero <<<(N_NODES + 255) / 256, 256, 0, s_b>>>();
        k_count<<<(E + 255) / 256, 256, 0, s_b>>>(ei, E);
        cudaEventRecord(ev_join, s_b);
        k_gemm1<<<(N_NODES + 127) / 128, 256>>>(x, W1);
        cudaStreamWaitEvent(main_s, ev_join, 0);
    } else {
        // sequential fallback (correctness call): same work, same results
        k_zero <<<(N_NODES + 255) / 256, 256>>>();
        k_count<<<(E + 255) / 256, 256>>>(ei, E);
        k_gemm1<<<(N_NODES + 127) / 128, 256>>>(x, W1);
    }

    k_init1<<<(N_NODES * (HDIM / 4) + 255) / 256, 256>>>();
    {
        long long tot = (long long)E * 16;
        k_scatter1<<<(int)((tot + 255) / 256), 256>>>(ei, E);
    }
    k_gemm2<<<(N_NODES + 127) / 128, 320>>>(W2, b1);
    {
        long long tot = (long long)E * 10;
        k_scatter2<<<(int)((tot + 255) / 256), 256>>>(ei, E);
    }
    k_final<<<(N_NODES * 32 + 255) / 256, 256>>>(b2, out);
}

// round 6
// speedup vs baseline: 1.3794x; 1.3794x over previous
#include <cuda_runtime.h>
#include <cuda_fp16.h>

#define N_NODES 100000
#define F_IN    128
#define HDIM    64
#define CDIM    40

// ---- scratch (device globals: no allocation allowed) ----
__device__ __align__(256) int    g_cnt [N_NODES];
__device__ __align__(256) float  g_dinv[N_NODES];
__device__ __align__(256) __half g_h1s [N_NODES * HDIM];  // (x@W1)*dinv[row], f16
__device__ __align__(256) __half g_agg1[N_NODES * HDIM];  // init=self, += h1s[src]
__device__ __align__(256) __half g_h2s [N_NODES * CDIM];
__device__ __align__(256) __half g_agg2[N_NODES * CDIM];

// ---------------------------------------------------------------- degree ----
__global__ void k_zero() {
    int i = blockIdx.x * blockDim.x + threadIdx.x;
    if (i < N_NODES) g_cnt[i] = 0;
}

__global__ void k_count(const int* __restrict__ ei, int E) {
    int e = blockIdx.x * blockDim.x + threadIdx.x;
    if (e >= E) return;
    int d = ei[E + e];
    if ((unsigned)d < (unsigned)N_NODES) atomicAdd(&g_cnt[d], 1);
}

__global__ void k_dinv() {
    int i = blockIdx.x * blockDim.x + threadIdx.x;
    if (i < N_NODES) g_dinv[i] = rsqrtf(1.0f + (float)g_cnt[i]);   // +1 self loop
}

// ------------------------------------------- GEMM1: h1s = (x@W1)*dinv  (f16 out)
// block 256 thr, tile 128 rows x 64 cols; thread: 8 rows x 4 cols, k-step 2
#define XPAD 36
__global__ __launch_bounds__(256, 3) void k_gemm1(const float* __restrict__ x,
                                                  const float* __restrict__ W1) {
    __shared__ float Ws[32 * 64];         // 8 KB
    __shared__ float Xs[128 * XPAD];      // 18.4 KB

    const int tid = threadIdx.x;
    const int cg  = tid & 15;             // cols cg*4 .. cg*4+3
    const int rg  = tid >> 4;             // rows rg*8 .. rg*8+7
    const int rowBase = blockIdx.x * 128;

    float4 acc[8];
    #pragma unroll
    for (int r = 0; r < 8; r++) acc[r] = make_float4(0.f, 0.f, 0.f, 0.f);

    for (int k0 = 0; k0 < F_IN; k0 += 32) {
        {   // stage W chunk [32][64]
            int r = tid >> 3, c = (tid & 7) * 8;
            float4 a = *(const float4*)&W1[(k0 + r) * HDIM + c];
            float4 b = *(const float4*)&W1[(k0 + r) * HDIM + c + 4];
            *(float4*)&Ws[r * 64 + c]     = a;
            *(float4*)&Ws[r * 64 + c + 4] = b;
        }
        {   // stage X chunk [128][32] into padded rows
            int r = tid >> 1, kk = (tid & 1) * 16;
            int row = rowBase + r;
            float* s = &Xs[r * XPAD + kk];
            if (row < N_NODES) {
                const float* xp = &x[(long long)row * F_IN + k0 + kk];
                *(float4*)(s)      = *(const float4*)(xp);
                *(float4*)(s + 4)  = *(const float4*)(xp + 4);
                *(float4*)(s + 8)  = *(const float4*)(xp + 8);
                *(float4*)(s + 12) = *(const float4*)(xp + 12);
            } else {
                *(float4*)(s)      = make_float4(0.f,0.f,0.f,0.f);
                *(float4*)(s + 4)  = make_float4(0.f,0.f,0.f,0.f);
                *(float4*)(s + 8)  = make_float4(0.f,0.f,0.f,0.f);
                *(float4*)(s + 12) = make_float4(0.f,0.f,0.f,0.f);
            }
        }
        __syncthreads();
        #pragma unroll
        for (int k = 0; k < 32; k += 2) {
            float4 w0 = *(const float4*)&Ws[k * 64 + cg * 4];
            float4 w1 = *(const float4*)&Ws[(k + 1) * 64 + cg * 4];
            #pragma unroll
            for (int r = 0; r < 8; r++) {
                float2 xv = *(const float2*)&Xs[(rg * 8 + r) * XPAD + k];
                acc[r].x += xv.x * w0.x; acc[r].y += xv.x * w0.y;
                acc[r].z += xv.x * w0.z; acc[r].w += xv.x * w0.w;
                acc[r].x += xv.y * w1.x; acc[r].y += xv.y * w1.y;
                acc[r].z += xv.y * w1.z; acc[r].w += xv.y * w1.w;
            }
        }
        __syncthreads();
    }

    #pragma unroll
    for (int r = 0; r < 8; r++) {
        int row = rowBase + rg * 8 + r;
        if (row < N_NODES) {
            float s = g_dinv[row];
            __half2 lo = __float22half2_rn(make_float2(acc[r].x * s, acc[r].y * s));
            __half2 hi = __float22half2_rn(make_float2(acc[r].z * s, acc[r].w * s));
            uint2 pk = make_uint2(*(unsigned*)&lo, *(unsigned*)&hi);   // 4 halves = 8B
            *(uint2*)&g_h1s [(long long)row * HDIM + cg * 4] = pk;
            *(uint2*)&g_agg1[(long long)row * HDIM + cg * 4] = pk;    // self-loop init
        }
    }
}

// ---------------------- scatter1: agg1[dst] += h1s[src]  (f16x2 vec reduction) ----
__global__ void k_scatter1(const int* __restrict__ ei, int E) {
    long long idx = (long long)blockIdx.x * blockDim.x + threadIdx.x;
    long long total = (long long)E * 8;           // 8 chunks of 8 halves (16B)
    if (idx >= total) return;
    int e = (int)(idx >> 3);
    int c = ((int)idx & 7) * 8;                   // half offset
    int s = ei[e], d = ei[E + e];
    if ((unsigned)s >= (unsigned)N_NODES || (unsigned)d >= (unsigned)N_NODES) return;
    uint4 v = *(const uint4*)&g_h1s[(long long)s * HDIM + c];
    __half* p = &g_agg1[(long long)d * HDIM + c];
    asm volatile("red.global.add.noftz.v4.f16x2 [%0], {%1, %2, %3, %4};"
                 :: "l"(p), "r"(v.x), "r"(v.y), "r"(v.z), "r"(v.w) : "memory");
}

// --------------------------- GEMM2: h2s = relu(dinv*agg1 + b1) @ W2 * dinv ----
__global__ __launch_bounds__(320) void k_gemm2(const float* __restrict__ W2,
                                               const float* __restrict__ b1) {
    __shared__ float Ws[64 * 40];
    __shared__ float Xs[128 * 65];
    __shared__ float Bs[64];

    const int tid = threadIdx.x;
    const int cg  = tid % 10;            // cols cg*4 .. cg*4+3
    const int rg  = tid / 10;            // rows rg*4 .. rg*4+3
    const int rowBase = blockIdx.x * 128;

    for (int i = tid; i < 64 * 40; i += 320) Ws[i] = W2[i];
    if (tid < 64) Bs[tid] = b1[tid];
    __syncthreads();

    // stage X: 128 rows x 64 k, reading half2 pairs (2 k per thread-iter)
    for (int i = tid; i < 128 * 32; i += 320) {
        int r = i >> 5, k2 = (i & 31) * 2;
        int row = rowBase + r;
        float2 v = make_float2(0.f, 0.f);
        if (row < N_NODES) {
            __half2 h = *(const __half2*)&g_agg1[(long long)row * HDIM + k2];
            float2 f = __half22float2(h);
            float di = g_dinv[row];
            v.x = fmaxf(di * f.x + Bs[k2],     0.f);
            v.y = fmaxf(di * f.y + Bs[k2 + 1], 0.f);
        }
        Xs[r * 65 + k2]     = v.x;
        Xs[r * 65 + k2 + 1] = v.y;
    }
    __syncthreads();

    float4 acc[4];
    #pragma unroll
    for (int r = 0; r < 4; r++) acc[r] = make_float4(0.f, 0.f, 0.f, 0.f);

    #pragma unroll 4
    for (int k = 0; k < 64; k++) {
        float4 w = *(const float4*)&Ws[k * 40 + cg * 4];
        #pragma unroll
        for (int r = 0; r < 4; r++) {
            float xv = Xs[(rg * 4 + r) * 65 + k];
            acc[r].x += xv * w.x; acc[r].y += xv * w.y;
            acc[r].z += xv * w.z; acc[r].w += xv * w.w;
        }
    }

    #pragma unroll
    for (int r = 0; r < 4; r++) {
        int row = rowBase + rg * 4 + r;
        if (row < N_NODES) {
            float s = g_dinv[row];
            __half2 lo = __float22half2_rn(make_float2(acc[r].x * s, acc[r].y * s));
            __half2 hi = __float22half2_rn(make_float2(acc[r].z * s, acc[r].w * s));
            uint2 pk = make_uint2(*(unsigned*)&lo, *(unsigned*)&hi);
            *(uint2*)&g_h2s [(long long)row * CDIM + cg * 4] = pk;
            *(uint2*)&g_agg2[(long long)row * CDIM + cg * 4] = pk;   // self-loop init
        }
    }
}

// ---------------------- scatter2: agg2[dst] += h2s[src]  (f16x2 vec reduction) ----
__global__ void k_scatter2(const int* __restrict__ ei, int E) {
    long long idx = (long long)blockIdx.x * blockDim.x + threadIdx.x;
    long long total = (long long)E * 5;           // 5 chunks of 8 halves (16B)
    if (idx >= total) return;
    int e = (int)(idx / 5);
    int c = (int)(idx % 5) * 8;                   // half offset
    int s = ei[e], d = ei[E + e];
    if ((unsigned)s >= (unsigned)N_NODES || (unsigned)d >= (unsigned)N_NODES) return;
    uint4 v = *(const uint4*)&g_h2s[(long long)s * CDIM + c];
    __half* p = &g_agg2[(long long)d * CDIM + c];
    asm volatile("red.global.add.noftz.v4.f16x2 [%0], {%1, %2, %3, %4};"
                 :: "l"(p), "r"(v.x), "r"(v.y), "r"(v.z), "r"(v.w) : "memory");
}

// -------------------------------------- final: out = log_softmax(dinv*agg2 + b2)
__global__ void k_final(const float* __restrict__ b2, float* __restrict__ out) {
    int gtid = blockIdx.x * blockDim.x + threadIdx.x;
    int row  = gtid >> 5;
    int lane = threadIdx.x & 31;
    if (row >= N_NODES) return;
    const __half* rp = &g_agg2[(long long)row * CDIM];
    float s  = g_dinv[row];
    float a0 = s * __half2float(rp[lane]) + b2[lane];
    float a1 = (lane < 8) ? (s * __half2float(rp[32 + lane]) + b2[32 + lane]) : -3.4e38f;
    float m  = fmaxf(a0, a1);
    #pragma unroll
    for (int o = 16; o; o >>= 1) m = fmaxf(m, __shfl_xor_sync(0xFFFFFFFFu, m, o));
    float es = expf(a0 - m) + ((lane < 8) ? expf(a1 - m) : 0.f);
    #pragma unroll
    for (int o = 16; o; o >>= 1) es += __shfl_xor_sync(0xFFFFFFFFu, es, o);
    float l = m + logf(es);
    out[(long long)row * CDIM + lane] = a0 - l;
    if (lane < 8) out[(long long)row * CDIM + 32 + lane] = a1 - l;
}

// ---------------------------------------------------------------------------
extern "C" void kernel_launch(void* const* d_in, const int* in_sizes, int n_in,
                              void* d_out, int out_size) {
    const float* x  = (const float*)d_in[0];
    const int*   ei = (const int*)  d_in[1];
    const float* W1 = (const float*)d_in[2];
    const float* b1 = (const float*)d_in[3];
    const float* W2 = (const float*)d_in[4];
    const float* b2 = (const float*)d_in[5];
    float* out = (float*)d_out;
    const int E = in_sizes[1] / 2;

    k_zero <<<(N_NODES + 255) / 256, 256>>>();
    k_count<<<(E + 255) / 256, 256>>>(ei, E);
    k_dinv <<<(N_NODES + 255) / 256, 256>>>();

    k_gemm1<<<(N_NODES + 127) / 128, 256>>>(x, W1);
    {
        long long tot = (long long)E * 8;
        k_scatter1<<<(int)((tot + 255) / 256), 256>>>(ei, E);
    }
    k_gemm2<<<(N_NODES + 127) / 128, 320>>>(W2, b1);
    {
        long long tot = (long long)E * 5;
        k_scatter2<<<(int)((tot + 255) / 256), 256>>>(ei, E);
    }
    k_final<<<(N_NODES * 32 + 255) / 256, 256>>>(b2, out);
}

// round 7
// speedup vs baseline: 1.5377x; 1.1148x over previous
#include <cuda_runtime.h>
#include <cuda_fp16.h>
#include <mma.h>
using namespace nvcuda;

#define N_NODES 100000
#define F_IN    128
#define HDIM    64
#define CDIM    40

// ---- scratch (device globals: no allocation allowed) ----
__device__ __align__(256) int    g_cnt [N_NODES];
__device__ __align__(256) float  g_dinv[N_NODES];
__device__ __align__(256) __half g_h1s [N_NODES * HDIM];  // (x@W1)*dinv[row], f16
__device__ __align__(256) __half g_agg1[N_NODES * HDIM];  // init=self, += h1s[src]
__device__ __align__(256) __half g_h2s [N_NODES * CDIM];
__device__ __align__(256) __half g_agg2[N_NODES * CDIM];

// ---------------------------------------------------------------- degree ----
__global__ void k_zero() {
    int i = blockIdx.x * blockDim.x + threadIdx.x;
    if (i < N_NODES) g_cnt[i] = 0;
}

__global__ void k_count(const int* __restrict__ ei, int E) {
    int e = blockIdx.x * blockDim.x + threadIdx.x;
    if (e >= E) return;
    int d = ei[E + e];
    if ((unsigned)d < (unsigned)N_NODES) atomicAdd(&g_cnt[d], 1);
}

__global__ void k_dinv() {
    int i = blockIdx.x * blockDim.x + threadIdx.x;
    if (i < N_NODES) g_dinv[i] = rsqrtf(1.0f + (float)g_cnt[i]);   // +1 self loop
}

// ------------------- GEMM1 (tensor cores): h1s = (x@W1)*dinv, f16 out ----------
// block 256 thr = 8 warps (4 m x 2 n), tile 128 rows x 64 cols, k-chunk 32
#define WN 72   // Wh row stride (halves), 144B = 9*16
#define XS 40   // Xh row stride (halves), 80B  = 5*16
#define ES 72   // Es row stride (floats), 288B = 18*16
__global__ __launch_bounds__(256, 2) void k_gemm1(const float* __restrict__ x,
                                                  const float* __restrict__ W1) {
    // union: [Wh 128*WN halves][Xh 128*XS halves]  <->  [Es 128*ES floats]
    __shared__ __align__(32) unsigned char sraw[128 * ES * 4];   // 36.9 KB
    __half* Wh = (__half*)sraw;
    __half* Xh = (__half*)(sraw + 128 * WN * 2);
    float*  Es = (float*)sraw;

    const int tid = threadIdx.x;
    const int wid = tid >> 5;
    const int warp_m = wid >> 1;          // 0..3 -> rows warp_m*32
    const int warp_n = wid & 1;           // 0..1 -> cols warp_n*32
    const int rowBase = blockIdx.x * 128;

    // convert whole W1 (128x64 fp32) to f16 smem
    for (int i = tid; i < 128 * 64; i += 256) {
        int k = i >> 6, n = i & 63;
        Wh[k * WN + n] = __float2half_rn(W1[i]);
    }

    wmma::fragment<wmma::accumulator, 16, 16, 16, float> c[2][2];
    #pragma unroll
    for (int i = 0; i < 2; i++)
        #pragma unroll
        for (int j = 0; j < 2; j++) wmma::fill_fragment(c[i][j], 0.f);

    for (int k0 = 0; k0 < F_IN; k0 += 32) {
        {   // stage Xh: 128 rows x 32 k (f32 -> f16)
            int r = tid >> 1, kk = (tid & 1) * 16;
            int row = rowBase + r;
            __half* s = &Xh[r * XS + kk];
            if (row < N_NODES) {
                const float* xp = &x[(long long)row * F_IN + k0 + kk];
                #pragma unroll
                for (int q = 0; q < 4; q++) {
                    float4 v = *(const float4*)(xp + q * 4);
                    __half2 h0 = __float22half2_rn(make_float2(v.x, v.y));
                    __half2 h1 = __float22half2_rn(make_float2(v.z, v.w));
                    *(__half2*)(s + q * 4)     = h0;
                    *(__half2*)(s + q * 4 + 2) = h1;
                }
            } else {
                #pragma unroll
                for (int q = 0; q < 8; q++)
                    *(__half2*)(s + q * 2) = __float2half2_rn(0.f);
            }
        }
        __syncthreads();   // Xh (and, first iter, Wh) visible

        #pragma unroll
        for (int kk = 0; kk < 32; kk += 16) {
            wmma::fragment<wmma::matrix_a, 16, 16, 16, __half, wmma::row_major> a[2];
            wmma::fragment<wmma::matrix_b, 16, 16, 16, __half, wmma::row_major> b[2];
            #pragma unroll
            for (int i = 0; i < 2; i++)
                wmma::load_matrix_sync(a[i], &Xh[(warp_m * 32 + i * 16) * XS + kk], XS);
            #pragma unroll
            for (int j = 0; j < 2; j++)
                wmma::load_matrix_sync(b[j], &Wh[(k0 + kk) * WN + warp_n * 32 + j * 16], WN);
            #pragma unroll
            for (int i = 0; i < 2; i++)
                #pragma unroll
                for (int j = 0; j < 2; j++)
                    wmma::mma_sync(c[i][j], a[i], b[j], c[i][j]);
        }
        __syncthreads();   // safe to restage Xh (and overwrite at end)
    }

    // dump accumulators (overwrites Wh/Xh region — all mma done per sync above)
    #pragma unroll
    for (int i = 0; i < 2; i++)
        #pragma unroll
        for (int j = 0; j < 2; j++)
            wmma::store_matrix_sync(&Es[(warp_m * 32 + i * 16) * ES + warp_n * 32 + j * 16],
                                    c[i][j], ES, wmma::mem_row_major);
    __syncthreads();

    {   // epilogue: scale by dinv, pack to f16, dual-store
        int r = tid >> 1, cb = (tid & 1) * 32;
        int row = rowBase + r;
        if (row < N_NODES) {
            float s = g_dinv[row];
            const float* ep = &Es[r * ES + cb];
            __half* d1 = &g_h1s [(long long)row * HDIM + cb];
            __half* d2 = &g_agg1[(long long)row * HDIM + cb];
            #pragma unroll
            for (int q = 0; q < 8; q++) {
                float4 v = *(const float4*)(ep + q * 4);
                __half2 h0 = __float22half2_rn(make_float2(v.x * s, v.y * s));
                __half2 h1 = __float22half2_rn(make_float2(v.z * s, v.w * s));
                uint2 pk = make_uint2(*(unsigned*)&h0, *(unsigned*)&h1);
                *(uint2*)(d1 + q * 4) = pk;
                *(uint2*)(d2 + q * 4) = pk;   // self-loop init
            }
        }
    }
}

// ---------------------- scatter1: agg1[dst] += h1s[src]  (f16x2 vec reduction) ----
__global__ void k_scatter1(const int* __restrict__ ei, int E) {
    long long idx = (long long)blockIdx.x * blockDim.x + threadIdx.x;
    long long total = (long long)E * 8;           // 8 chunks of 8 halves (16B)
    if (idx >= total) return;
    int e = (int)(idx >> 3);
    int c = ((int)idx & 7) * 8;                   // half offset
    int s = ei[e], d = ei[E + e];
    if ((unsigned)s >= (unsigned)N_NODES || (unsigned)d >= (unsigned)N_NODES) return;
    uint4 v = *(const uint4*)&g_h1s[(long long)s * HDIM + c];
    __half* p = &g_agg1[(long long)d * HDIM + c];
    asm volatile("red.global.add.noftz.v4.f16x2 [%0], {%1, %2, %3, %4};"
                 :: "l"(p), "r"(v.x), "r"(v.y), "r"(v.z), "r"(v.w) : "memory");
}

// --------------------------- GEMM2: h2s = relu(dinv*agg1 + b1) @ W2 * dinv ----
__global__ __launch_bounds__(320) void k_gemm2(const float* __restrict__ W2,
                                               const float* __restrict__ b1) {
    __shared__ float Ws[64 * 40];
    __shared__ float Xs[128 * 65];
    __shared__ float Bs[64];

    const int tid = threadIdx.x;
    const int cg  = tid % 10;            // cols cg*4 .. cg*4+3
    const int rg  = tid / 10;            // rows rg*4 .. rg*4+3
    const int rowBase = blockIdx.x * 128;

    for (int i = tid; i < 64 * 40; i += 320) Ws[i] = W2[i];
    if (tid < 64) Bs[tid] = b1[tid];
    __syncthreads();

    for (int i = tid; i < 128 * 32; i += 320) {
        int r = i >> 5, k2 = (i & 31) * 2;
        int row = rowBase + r;
        float2 v = make_float2(0.f, 0.f);
        if (row < N_NODES) {
            __half2 h = *(const __half2*)&g_agg1[(long long)row * HDIM + k2];
            float2 f = __half22float2(h);
            float di = g_dinv[row];
            v.x = fmaxf(di * f.x + Bs[k2],     0.f);
            v.y = fmaxf(di * f.y + Bs[k2 + 1], 0.f);
        }
        Xs[r * 65 + k2]     = v.x;
        Xs[r * 65 + k2 + 1] = v.y;
    }
    __syncthreads();

    float4 acc[4];
    #pragma unroll
    for (int r = 0; r < 4; r++) acc[r] = make_float4(0.f, 0.f, 0.f, 0.f);

    #pragma unroll 4
    for (int k = 0; k < 64; k++) {
        float4 w = *(const float4*)&Ws[k * 40 + cg * 4];
        #pragma unroll
        for (int r = 0; r < 4; r++) {
            float xv = Xs[(rg * 4 + r) * 65 + k];
            acc[r].x += xv * w.x; acc[r].y += xv * w.y;
            acc[r].z += xv * w.z; acc[r].w += xv * w.w;
        }
    }

    #pragma unroll
    for (int r = 0; r < 4; r++) {
        int row = rowBase + rg * 4 + r;
        if (row < N_NODES) {
            float s = g_dinv[row];
            __half2 lo = __float22half2_rn(make_float2(acc[r].x * s, acc[r].y * s));
            __half2 hi = __float22half2_rn(make_float2(acc[r].z * s, acc[r].w * s));
            uint2 pk = make_uint2(*(unsigned*)&lo, *(unsigned*)&hi);
            *(uint2*)&g_h2s [(long long)row * CDIM + cg * 4] = pk;
            *(uint2*)&g_agg2[(long long)row * CDIM + cg * 4] = pk;   // self-loop init
        }
    }
}

// ---------------------- scatter2: agg2[dst] += h2s[src]  (f16x2 vec reduction) ----
__global__ void k_scatter2(const int* __restrict__ ei, int E) {
    long long idx = (long long)blockIdx.x * blockDim.x + threadIdx.x;
    long long total = (long long)E * 5;           // 5 chunks of 8 halves (16B)
    if (idx >= total) return;
    int e = (int)(idx / 5);
    int c = (int)(idx % 5) * 8;                   // half offset
    int s = ei[e], d = ei[E + e];
    if ((unsigned)s >= (unsigned)N_NODES || (unsigned)d >= (unsigned)N_NODES) return;
    uint4 v = *(const uint4*)&g_h2s[(long long)s * CDIM + c];
    __half* p = &g_agg2[(long long)d * CDIM + c];
    asm volatile("red.global.add.noftz.v4.f16x2 [%0], {%1, %2, %3, %4};"
                 :: "l"(p), "r"(v.x), "r"(v.y), "r"(v.z), "r"(v.w) : "memory");
}

// -------------------------------------- final: out = log_softmax(dinv*agg2 + b2)
__global__ void k_final(const float* __restrict__ b2, float* __restrict__ out) {
    int gtid = blockIdx.x * blockDim.x + threadIdx.x;
    int row  = gtid >> 5;
    int lane = threadIdx.x & 31;
    if (row >= N_NODES) return;
    const __half* rp = &g_agg2[(long long)row * CDIM];
    float s  = g_dinv[row];
    float a0 = s * __half2float(rp[lane]) + b2[lane];
    float a1 = (lane < 8) ? (s * __half2float(rp[32 + lane]) + b2[32 + lane]) : -3.4e38f;
    float m  = fmaxf(a0, a1);
    #pragma unroll
    for (int o = 16; o; o >>= 1) m = fmaxf(m, __shfl_xor_sync(0xFFFFFFFFu, m, o));
    float es = expf(a0 - m) + ((lane < 8) ? expf(a1 - m) : 0.f);
    #pragma unroll
    for (int o = 16; o; o >>= 1) es += __shfl_xor_sync(0xFFFFFFFFu, es, o);
    float l = m + logf(es);
    out[(long long)row * CDIM + lane] = a0 - l;
    if (lane < 8) out[(long long)row * CDIM + 32 + lane] = a1 - l;
}

// ---------------------------------------------------------------------------
extern "C" void kernel_launch(void* const* d_in, const int* in_sizes, int n_in,
                              void* d_out, int out_size) {
    const float* x  = (const float*)d_in[0];
    const int*   ei = (const int*)  d_in[1];
    const float* W1 = (const float*)d_in[2];
    const float* b1 = (const float*)d_in[3];
    const float* W2 = (const float*)d_in[4];
    const float* b2 = (const float*)d_in[5];
    float* out = (float*)d_out;
    const int E = in_sizes[1] / 2;

    k_zero <<<(N_NODES + 255) / 256, 256>>>();
    k_count<<<(E + 255) / 256, 256>>>(ei, E);
    k_dinv <<<(N_NODES + 255) / 256, 256>>>();

    k_gemm1<<<(N_NODES + 127) / 128, 256>>>(x, W1);
    {
        long long tot = (long long)E * 8;
        k_scatter1<<<(int)((tot + 255) / 256), 256>>>(ei, E);
    }
    k_gemm2<<<(N_NODES + 127) / 128, 320>>>(W2, b1);
    {
        long long tot = (long long)E * 5;
        k_scatter2<<<(int)((tot + 255) / 256), 256>>>(ei, E);
    }
    k_final<<<(N_NODES * 32 + 255) / 256, 256>>>(b2, out);
}

// round 8
// speedup vs baseline: 1.6753x; 1.0895x over previous
#include <cuda_runtime.h>
#include <cuda_fp16.h>
#include <mma.h>
using namespace nvcuda;

#define N_NODES 100000
#define F_IN    128
#define HDIM    64
#define CDIM    40

// ---- scratch (device globals: no allocation allowed) ----
__device__ __align__(256) int    g_cnt [N_NODES];
__device__ __align__(256) float  g_dinv[N_NODES];
__device__ __align__(256) __half g_h1s [N_NODES * HDIM];  // (x@W1)*dinv[row], f16
__device__ __align__(256) __half g_agg1[N_NODES * HDIM];  // init=self, += h1s[src]
__device__ __align__(256) __half g_h2s [N_NODES * CDIM];
__device__ __align__(256) __half g_agg2[N_NODES * CDIM];

// ---------------------------------------------------------------- degree ----
__global__ void k_zero() {
    int i = blockIdx.x * blockDim.x + threadIdx.x;
    if (i < N_NODES) g_cnt[i] = 0;
}

__global__ void k_count(const int* __restrict__ ei, int E) {
    int e = blockIdx.x * blockDim.x + threadIdx.x;
    if (e >= E) return;
    int d = ei[E + e];
    if ((unsigned)d < (unsigned)N_NODES) atomicAdd(&g_cnt[d], 1);
}

// ---- GEMM1 (tensor cores, pipelined): h1s = (x@W1)*dinv, also writes g_dinv ----
// block 256 thr = 8 warps (4 m x 2 n), tile 128 rows x 64 cols, k-chunk 32 x4
#define WN 72   // Wh row stride (halves), 144B
#define XS 40   // Xh row stride (halves), 80B
#define ES 72   // Es row stride (floats), 288B
#define G1_SMEM (128*WN*2 + 2*128*XS*2)   // 18432 + 20480 = 38912 > Es 36864
__global__ __launch_bounds__(256, 2) void k_gemm1(const float* __restrict__ x,
                                                  const float* __restrict__ W1) {
    __shared__ __align__(32) unsigned char sraw[G1_SMEM];
    __half* Wh  = (__half*)sraw;
    __half* Xh0 = (__half*)(sraw + 128 * WN * 2);
    __half* Xh1 = (__half*)(sraw + 128 * WN * 2 + 128 * XS * 2);
    float*  Es  = (float*)sraw;

    const int tid = threadIdx.x;
    const int wid = tid >> 5;
    const int warp_m = wid >> 1;          // rows warp_m*32
    const int warp_n = wid & 1;           // cols warp_n*32
    const int rowBase = blockIdx.x * 128;

    const int srow  = tid >> 1;                    // staging row 0..127
    const int kkOff = (tid & 1) * 16;              // staging k sub-offset
    const int grow  = rowBase + srow;
    const bool rowOK = (grow < N_NODES);
    const float* xrow = &x[(long long)grow * F_IN + kkOff];

    // convert whole W1 (128x64 fp32) to f16 smem
    for (int i = tid; i < 128 * 64; i += 256) {
        int k = i >> 6, n = i & 63;
        Wh[k * WN + n] = __float2half_rn(W1[i]);
    }

    // stage chunk 0 into Xh0
    {
        __half* s = &Xh0[srow * XS + kkOff];
        if (rowOK) {
            #pragma unroll
            for (int q = 0; q < 4; q++) {
                float4 v = *(const float4*)(xrow + q * 4);
                *(__half2*)(s + q * 4)     = __float22half2_rn(make_float2(v.x, v.y));
                *(__half2*)(s + q * 4 + 2) = __float22half2_rn(make_float2(v.z, v.w));
            }
        } else {
            #pragma unroll
            for (int q = 0; q < 8; q++) *(__half2*)(s + q * 2) = __float2half2_rn(0.f);
        }
    }

    wmma::fragment<wmma::accumulator, 16, 16, 16, float> c[2][2];
    #pragma unroll
    for (int i = 0; i < 2; i++)
        #pragma unroll
        for (int j = 0; j < 2; j++) wmma::fill_fragment(c[i][j], 0.f);

    __syncthreads();

    #pragma unroll
    for (int ch = 0; ch < 4; ch++) {
        // prefetch next chunk into registers (overlaps with mma below)
        float4 p0, p1, p2, p3;
        if (ch < 3 && rowOK) {
            const float* xp = xrow + (ch + 1) * 32;
            p0 = *(const float4*)(xp);
            p1 = *(const float4*)(xp + 4);
            p2 = *(const float4*)(xp + 8);
            p3 = *(const float4*)(xp + 12);
        }

        const __half* Xb = (ch & 1) ? Xh1 : Xh0;
        #pragma unroll
        for (int kk = 0; kk < 32; kk += 16) {
            wmma::fragment<wmma::matrix_a, 16, 16, 16, __half, wmma::row_major> a[2];
            wmma::fragment<wmma::matrix_b, 16, 16, 16, __half, wmma::row_major> b[2];
            #pragma unroll
            for (int i = 0; i < 2; i++)
                wmma::load_matrix_sync(a[i], &Xb[(warp_m * 32 + i * 16) * XS + kk], XS);
            #pragma unroll
            for (int j = 0; j < 2; j++)
                wmma::load_matrix_sync(b[j], &Wh[(ch * 32 + kk) * WN + warp_n * 32 + j * 16], WN);
            #pragma unroll
            for (int i = 0; i < 2; i++)
                #pragma unroll
                for (int j = 0; j < 2; j++)
                    wmma::mma_sync(c[i][j], a[i], b[j], c[i][j]);
        }

        if (ch < 3) {
            __half* s = ((ch & 1) ? Xh0 : Xh1) + srow * XS + kkOff;
            if (rowOK) {
                *(__half2*)(s)      = __float22half2_rn(make_float2(p0.x, p0.y));
                *(__half2*)(s + 2)  = __float22half2_rn(make_float2(p0.z, p0.w));
                *(__half2*)(s + 4)  = __float22half2_rn(make_float2(p1.x, p1.y));
                *(__half2*)(s + 6)  = __float22half2_rn(make_float2(p1.z, p1.w));
                *(__half2*)(s + 8)  = __float22half2_rn(make_float2(p2.x, p2.y));
                *(__half2*)(s + 10) = __float22half2_rn(make_float2(p2.z, p2.w));
                *(__half2*)(s + 12) = __float22half2_rn(make_float2(p3.x, p3.y));
                *(__half2*)(s + 14) = __float22half2_rn(make_float2(p3.z, p3.w));
            } else {
                #pragma unroll
                for (int q = 0; q < 8; q++) *(__half2*)(s + q * 2) = __float2half2_rn(0.f);
            }
        }
        __syncthreads();
    }

    // dump accumulators to Es (smem reuse is safe: all mma done, sync above)
    #pragma unroll
    for (int i = 0; i < 2; i++)
        #pragma unroll
        for (int j = 0; j < 2; j++)
            wmma::store_matrix_sync(&Es[(warp_m * 32 + i * 16) * ES + warp_n * 32 + j * 16],
                                    c[i][j], ES, wmma::mem_row_major);
    __syncthreads();

    {   // epilogue: compute dinv inline, scale, pack f16, dual-store
        int cb = (tid & 1) * 32;
        if (rowOK) {
            float s = rsqrtf(1.0f + (float)g_cnt[grow]);
            if (cb == 0) g_dinv[grow] = s;
            const float* ep = &Es[srow * ES + cb];
            __half* d1 = &g_h1s [(long long)grow * HDIM + cb];
            __half* d2 = &g_agg1[(long long)grow * HDIM + cb];
            #pragma unroll
            for (int q = 0; q < 8; q++) {
                float4 v = *(const float4*)(ep + q * 4);
                __half2 h0 = __float22half2_rn(make_float2(v.x * s, v.y * s));
                __half2 h1 = __float22half2_rn(make_float2(v.z * s, v.w * s));
                uint2 pk = make_uint2(*(unsigned*)&h0, *(unsigned*)&h1);
                *(uint2*)(d1 + q * 4) = pk;
                *(uint2*)(d2 + q * 4) = pk;   // self-loop init
            }
        }
    }
}

// ---------------------- scatter1: agg1[dst] += h1s[src]  (f16x2 vec reduction) ----
__global__ void k_scatter1(const int* __restrict__ ei, int E) {
    long long idx = (long long)blockIdx.x * blockDim.x + threadIdx.x;
    long long total = (long long)E * 8;           // 8 chunks of 8 halves (16B)
    if (idx >= total) return;
    int e = (int)(idx >> 3);
    int c = ((int)idx & 7) * 8;                   // half offset
    int s = ei[e], d = ei[E + e];
    if ((unsigned)s >= (unsigned)N_NODES || (unsigned)d >= (unsigned)N_NODES) return;
    uint4 v = *(const uint4*)&g_h1s[(long long)s * HDIM + c];
    __half* p = &g_agg1[(long long)d * HDIM + c];
    asm volatile("red.global.add.noftz.v4.f16x2 [%0], {%1, %2, %3, %4};"
                 :: "l"(p), "r"(v.x), "r"(v.y), "r"(v.z), "r"(v.w) : "memory");
}

// ---- GEMM2 (tensor cores): h2s = relu(dinv*agg1 + b1) @ W2 * dinv, f16 out ----
// block 256 thr = 8 warps; warp w handles rows w*16..w*16+15, all 48 (padded) cols
#define W2S 56   // Wh2 row stride (halves), 112B
#define X2S 72   // Xh2 row stride (halves), 144B
#define E2S 56   // Es2 row stride (floats), 224B
#define G2_SMEM (128 * E2S * 4)   // 28672 >= 64*W2S*2 + 128*X2S*2 = 7168+18432=25600
__global__ __launch_bounds__(256, 2) void k_gemm2(const float* __restrict__ W2,
                                                  const float* __restrict__ b1) {
    __shared__ __align__(32) unsigned char sraw[G2_SMEM];
    __half* Wh = (__half*)sraw;
    __half* Xh = (__half*)(sraw + 64 * W2S * 2);
    float*  Es = (float*)sraw;
    __shared__ float Bs[64];

    const int tid = threadIdx.x;
    const int wid = tid >> 5;
    const int rowBase = blockIdx.x * 128;
    const int srow = tid >> 1;
    const int grow = rowBase + srow;
    const bool rowOK = (grow < N_NODES);

    // stage W2 (64x40 f32) -> Wh [64][48 padded]
    for (int i = tid; i < 64 * 48; i += 256) {
        int k = i / 48, n = i % 48;
        Wh[k * W2S + n] = __float2half_rn(n < 40 ? W2[k * 40 + n] : 0.f);
    }
    if (tid < 64) Bs[tid] = b1[tid];
    __syncthreads();   // Bs ready before staging uses it

    {   // stage Xh: relu(dinv*agg1 + b1) -> f16, 2 threads/row x 32 k
        int kb = (tid & 1) * 32;
        __half* s = &Xh[srow * X2S + kb];
        if (rowOK) {
            float di = g_dinv[grow];
            const __half2* ap = (const __half2*)&g_agg1[(long long)grow * HDIM + kb];
            #pragma unroll
            for (int q = 0; q < 16; q++) {
                float2 f = __half22float2(ap[q]);
                float2 v = make_float2(fmaxf(di * f.x + Bs[kb + q*2],     0.f),
                                       fmaxf(di * f.y + Bs[kb + q*2 + 1], 0.f));
                *(__half2*)(s + q * 2) = __float22half2_rn(v);
            }
        } else {
            #pragma unroll
            for (int q = 0; q < 16; q++) *(__half2*)(s + q * 2) = __float2half2_rn(0.f);
        }
    }
    __syncthreads();

    wmma::fragment<wmma::accumulator, 16, 16, 16, float> c[3];
    #pragma unroll
    for (int j = 0; j < 3; j++) wmma::fill_fragment(c[j], 0.f);

    #pragma unroll
    for (int k = 0; k < 64; k += 16) {
        wmma::fragment<wmma::matrix_a, 16, 16, 16, __half, wmma::row_major> a;
        wmma::load_matrix_sync(a, &Xh[(wid * 16) * X2S + k], X2S);
        #pragma unroll
        for (int j = 0; j < 3; j++) {
            wmma::fragment<wmma::matrix_b, 16, 16, 16, __half, wmma::row_major> b;
            wmma::load_matrix_sync(b, &Wh[k * W2S + j * 16], W2S);
            wmma::mma_sync(c[j], a, b, c[j]);
        }
    }
    __syncthreads();   // all reads of Wh/Xh done before Es overwrite

    #pragma unroll
    for (int j = 0; j < 3; j++)
        wmma::store_matrix_sync(&Es[(wid * 16) * E2S + j * 16], c[j], E2S,
                                wmma::mem_row_major);
    __syncthreads();

    {   // epilogue: scale by dinv, pack f16, dual-store (2 thr/row x 20 cols)
        int cb = (tid & 1) * 20;
        if (rowOK) {
            float s = g_dinv[grow];
            const float* ep = &Es[srow * E2S + cb];
            __half* d1 = &g_h2s [(long long)grow * CDIM + cb];
            __half* d2 = &g_agg2[(long long)grow * CDIM + cb];
            #pragma unroll
            for (int q = 0; q < 5; q++) {
                float4 v = *(const float4*)(ep + q * 4);
                __half2 h0 = __float22half2_rn(make_float2(v.x * s, v.y * s));
                __half2 h1 = __float22half2_rn(make_float2(v.z * s, v.w * s));
                uint2 pk = make_uint2(*(unsigned*)&h0, *(unsigned*)&h1);
                *(uint2*)(d1 + q * 4) = pk;
                *(uint2*)(d2 + q * 4) = pk;   // self-loop init
            }
        }
    }
}

// ---------------------- scatter2: agg2[dst] += h2s[src]  (f16x2 vec reduction) ----
__global__ void k_scatter2(const int* __restrict__ ei, int E) {
    long long idx = (long long)blockIdx.x * blockDim.x + threadIdx.x;
    long long total = (long long)E * 5;           // 5 chunks of 8 halves (16B)
    if (idx >= total) return;
    int e = (int)(idx / 5);
    int c = (int)(idx % 5) * 8;                   // half offset
    int s = ei[e], d = ei[E + e];
    if ((unsigned)s >= (unsigned)N_NODES || (unsigned)d >= (unsigned)N_NODES) return;
    uint4 v = *(const uint4*)&g_h2s[(long long)s * CDIM + c];
    __half* p = &g_agg2[(long long)d * CDIM + c];
    asm volatile("red.global.add.noftz.v4.f16x2 [%0], {%1, %2, %3, %4};"
                 :: "l"(p), "r"(v.x), "r"(v.y), "r"(v.z), "r"(v.w) : "memory");
}

// -------------------------------------- final: out = log_softmax(dinv*agg2 + b2)
__global__ void k_final(const float* __restrict__ b2, float* __restrict__ out) {
    int gtid = blockIdx.x * blockDim.x + threadIdx.x;
    int row  = gtid >> 5;
    int lane = threadIdx.x & 31;
    if (row >= N_NODES) return;
    const __half* rp = &g_agg2[(long long)row * CDIM];
    float s  = g_dinv[row];
    float a0 = s * __half2float(rp[lane]) + b2[lane];
    float a1 = (lane < 8) ? (s * __half2float(rp[32 + lane]) + b2[32 + lane]) : -3.4e38f;
    float m  = fmaxf(a0, a1);
    #pragma unroll
    for (int o = 16; o; o >>= 1) m = fmaxf(m, __shfl_xor_sync(0xFFFFFFFFu, m, o));
    float es = expf(a0 - m) + ((lane < 8) ? expf(a1 - m) : 0.f);
    #pragma unroll
    for (int o = 16; o; o >>= 1) es += __shfl_xor_sync(0xFFFFFFFFu, es, o);
    float l = m + logf(es);
    out[(long long)row * CDIM + lane] = a0 - l;
    if (lane < 8) out[(long long)row * CDIM + 32 + lane] = a1 - l;
}

// ---------------------------------------------------------------------------
extern "C" void kernel_launch(void* const* d_in, const int* in_sizes, int n_in,
                              void* d_out, int out_size) {
    const float* x  = (const float*)d_in[0];
    const int*   ei = (const int*)  d_in[1];
    const float* W1 = (const float*)d_in[2];
    const float* b1 = (const float*)d_in[3];
    const float* W2 = (const float*)d_in[4];
    const float* b2 = (const float*)d_in[5];
    float* out = (float*)d_out;
    const int E = in_sizes[1] / 2;

    k_zero <<<(N_NODES + 255) / 256, 256>>>();
    k_count<<<(E + 255) / 256, 256>>>(ei, E);

    k_gemm1<<<(N_NODES + 127) / 128, 256>>>(x, W1);
    {
        long long tot = (long long)E * 8;
        k_scatter1<<<(int)((tot + 255) / 256), 256>>>(ei, E);
    }
    k_gemm2<<<(N_NODES + 127) / 128, 256>>>(W2, b1);
    {
        long long tot = (long long)E * 5;
        k_scatter2<<<(int)((tot + 255) / 256), 256>>>(ei, E);
    }
    k_final<<<(N_NODES * 32 + 255) / 256, 256>>>(b2, out);
}

// round 9
// speedup vs baseline: 1.6942x; 1.0113x over previous
#include <cuda_runtime.h>
#include <cuda_fp16.h>
#include <mma.h>
using namespace nvcuda;

#define N_NODES 100000
#define F_IN    128
#define HDIM    64
#define CDIM    40

// ---- scratch (device globals: no allocation allowed) ----
__device__ __align__(256) int    g_cnt [N_NODES];
__device__ __align__(256) float  g_dinv[N_NODES];
__device__ __align__(256) __half g_h1s [N_NODES * HDIM];  // (x@W1)*dinv[row], f16
__device__ __align__(256) __half g_agg1[N_NODES * HDIM];  // init=self, += h1s[src]
__device__ __align__(256) __half g_h2s [N_NODES * CDIM];
__device__ __align__(256) __half g_agg2[N_NODES * CDIM];

// ---------------------------------------------------------------- degree ----
__global__ void k_count(const int* __restrict__ ei, int E) {
    int e = blockIdx.x * blockDim.x + threadIdx.x;
    if (e >= E) return;
    int d = __ldcg(&ei[E + e]);
    if ((unsigned)d < (unsigned)N_NODES) atomicAdd(&g_cnt[d], 1);
}

// ---- GEMM1 (tensor cores, pipelined): h1s = (x@W1)*dinv, also writes g_dinv ----
// block 256 thr = 8 warps (4 m x 2 n), tile 128 rows x 64 cols, k-chunk 32 x4
#define WN 72   // Wh row stride (halves), 144B
#define XS 40   // Xh row stride (halves), 80B
#define ES 72   // Es row stride (floats), 288B
#define G1_SMEM (128*WN*2 + 2*128*XS*2)
__global__ __launch_bounds__(256, 2) void k_gemm1(const float* __restrict__ x,
                                                  const float* __restrict__ W1) {
    __shared__ __align__(32) unsigned char sraw[G1_SMEM];
    __half* Wh  = (__half*)sraw;
    __half* Xh0 = (__half*)(sraw + 128 * WN * 2);
    __half* Xh1 = (__half*)(sraw + 128 * WN * 2 + 128 * XS * 2);
    float*  Es  = (float*)sraw;

    const int tid = threadIdx.x;
    const int wid = tid >> 5;
    const int warp_m = wid >> 1;
    const int warp_n = wid & 1;
    const int rowBase = blockIdx.x * 128;

    const int srow  = tid >> 1;
    const int kkOff = (tid & 1) * 16;
    const int grow  = rowBase + srow;
    const bool rowOK = (grow < N_NODES);
    const float* xrow = &x[(long long)grow * F_IN + kkOff];

    for (int i = tid; i < 128 * 64; i += 256) {
        int k = i >> 6, n = i & 63;
        Wh[k * WN + n] = __float2half_rn(W1[i]);
    }

    {   // stage chunk 0 into Xh0
        __half* s = &Xh0[srow * XS + kkOff];
        if (rowOK) {
            #pragma unroll
            for (int q = 0; q < 4; q++) {
                float4 v = *(const float4*)(xrow + q * 4);
                *(__half2*)(s + q * 4)     = __float22half2_rn(make_float2(v.x, v.y));
                *(__half2*)(s + q * 4 + 2) = __float22half2_rn(make_float2(v.z, v.w));
            }
        } else {
            #pragma unroll
            for (int q = 0; q < 8; q++) *(__half2*)(s + q * 2) = __float2half2_rn(0.f);
        }
    }

    wmma::fragment<wmma::accumulator, 16, 16, 16, float> c[2][2];
    #pragma unroll
    for (int i = 0; i < 2; i++)
        #pragma unroll
        for (int j = 0; j < 2; j++) wmma::fill_fragment(c[i][j], 0.f);

    __syncthreads();

    #pragma unroll
    for (int ch = 0; ch < 4; ch++) {
        float4 p0, p1, p2, p3;
        if (ch < 3 && rowOK) {
            const float* xp = xrow + (ch + 1) * 32;
            p0 = *(const float4*)(xp);
            p1 = *(const float4*)(xp + 4);
            p2 = *(const float4*)(xp + 8);
            p3 = *(const float4*)(xp + 12);
        }

        const __half* Xb = (ch & 1) ? Xh1 : Xh0;
        #pragma unroll
        for (int kk = 0; kk < 32; kk += 16) {
            wmma::fragment<wmma::matrix_a, 16, 16, 16, __half, wmma::row_major> a[2];
            wmma::fragment<wmma::matrix_b, 16, 16, 16, __half, wmma::row_major> b[2];
            #pragma unroll
            for (int i = 0; i < 2; i++)
                wmma::load_matrix_sync(a[i], &Xb[(warp_m * 32 + i * 16) * XS + kk], XS);
            #pragma unroll
            for (int j = 0; j < 2; j++)
                wmma::load_matrix_sync(b[j], &Wh[(ch * 32 + kk) * WN + warp_n * 32 + j * 16], WN);
            #pragma unroll
            for (int i = 0; i < 2; i++)
                #pragma unroll
                for (int j = 0; j < 2; j++)
                    wmma::mma_sync(c[i][j], a[i], b[j], c[i][j]);
        }

        if (ch < 3) {
            __half* s = ((ch & 1) ? Xh0 : Xh1) + srow * XS + kkOff;
            if (rowOK) {
                *(__half2*)(s)      = __float22half2_rn(make_float2(p0.x, p0.y));
                *(__half2*)(s + 2)  = __float22half2_rn(make_float2(p0.z, p0.w));
                *(__half2*)(s + 4)  = __float22half2_rn(make_float2(p1.x, p1.y));
                *(__half2*)(s + 6)  = __float22half2_rn(make_float2(p1.z, p1.w));
                *(__half2*)(s + 8)  = __float22half2_rn(make_float2(p2.x, p2.y));
                *(__half2*)(s + 10) = __float22half2_rn(make_float2(p2.z, p2.w));
                *(__half2*)(s + 12) = __float22half2_rn(make_float2(p3.x, p3.y));
                *(__half2*)(s + 14) = __float22half2_rn(make_float2(p3.z, p3.w));
            } else {
                #pragma unroll
                for (int q = 0; q < 8; q++) *(__half2*)(s + q * 2) = __float2half2_rn(0.f);
            }
        }
        __syncthreads();
    }

    #pragma unroll
    for (int i = 0; i < 2; i++)
        #pragma unroll
        for (int j = 0; j < 2; j++)
            wmma::store_matrix_sync(&Es[(warp_m * 32 + i * 16) * ES + warp_n * 32 + j * 16],
                                    c[i][j], ES, wmma::mem_row_major);
    __syncthreads();

    {   // epilogue: dinv inline, scale, pack f16, dual-store
        int cb = (tid & 1) * 32;
        if (rowOK) {
            float s = rsqrtf(1.0f + (float)g_cnt[grow]);
            if (cb == 0) g_dinv[grow] = s;
            const float* ep = &Es[srow * ES + cb];
            __half* d1 = &g_h1s [(long long)grow * HDIM + cb];
            __half* d2 = &g_agg1[(long long)grow * HDIM + cb];
            #pragma unroll
            for (int q = 0; q < 8; q++) {
                float4 v = *(const float4*)(ep + q * 4);
                __half2 h0 = __float22half2_rn(make_float2(v.x * s, v.y * s));
                __half2 h1 = __float22half2_rn(make_float2(v.z * s, v.w * s));
                uint2 pk = make_uint2(*(unsigned*)&h0, *(unsigned*)&h1);
                *(uint2*)(d1 + q * 4) = pk;
                *(uint2*)(d2 + q * 4) = pk;
            }
        }
    }
}

// -------- scatter1: agg1[dst] += h1s[src], 2 independent chains per thread ------
__device__ __forceinline__ void sc1_one(const int* __restrict__ ei, int E, long long idx) {
    int e = (int)(idx >> 3);
    int c = ((int)idx & 7) * 8;
    int s = __ldcg(&ei[e]), d = __ldcg(&ei[E + e]);
    if ((unsigned)s >= (unsigned)N_NODES || (unsigned)d >= (unsigned)N_NODES) return;
    uint4 v = __ldcg((const uint4*)&g_h1s[(long long)s * HDIM + c]);
    __half* p = &g_agg1[(long long)d * HDIM + c];
    asm volatile("red.global.add.noftz.v4.f16x2 [%0], {%1, %2, %3, %4};"
                 :: "l"(p), "r"(v.x), "r"(v.y), "r"(v.z), "r"(v.w) : "memory");
}

__global__ void k_scatter1(const int* __restrict__ ei, int E) {
    long long half = ((long long)E * 8) >> 1;
    long long idx = (long long)blockIdx.x * blockDim.x + threadIdx.x;
    if (idx >= half) return;
    sc1_one(ei, E, idx);
    sc1_one(ei, E, idx + half);
}

// ---- GEMM2 (tensor cores): h2s = relu(dinv*agg1 + b1) @ W2 * dinv, f16 out ----
#define W2S 56
#define X2S 72
#define E2S 56
#define G2_SMEM (128 * E2S * 4)
__global__ __launch_bounds__(256, 2) void k_gemm2(const float* __restrict__ W2,
                                                  const float* __restrict__ b1) {
    __shared__ __align__(32) unsigned char sraw[G2_SMEM];
    __half* Wh = (__half*)sraw;
    __half* Xh = (__half*)(sraw + 64 * W2S * 2);
    float*  Es = (float*)sraw;
    __shared__ float Bs[64];

    const int tid = threadIdx.x;
    const int wid = tid >> 5;
    const int rowBase = blockIdx.x * 128;
    const int srow = tid >> 1;
    const int grow = rowBase + srow;
    const bool rowOK = (grow < N_NODES);

    for (int i = tid; i < 64 * 48; i += 256) {
        int k = i / 48, n = i % 48;
        Wh[k * W2S + n] = __float2half_rn(n < 40 ? W2[k * 40 + n] : 0.f);
    }
    if (tid < 64) Bs[tid] = b1[tid];
    __syncthreads();

    {   // stage Xh: relu(dinv*agg1 + b1) -> f16
        int kb = (tid & 1) * 32;
        __half* s = &Xh[srow * X2S + kb];
        if (rowOK) {
            float di = g_dinv[grow];
            const __half2* ap = (const __half2*)&g_agg1[(long long)grow * HDIM + kb];
            #pragma unroll
            for (int q = 0; q < 16; q++) {
                float2 f = __half22float2(ap[q]);
                float2 v = make_float2(fmaxf(di * f.x + Bs[kb + q*2],     0.f),
                                       fmaxf(di * f.y + Bs[kb + q*2 + 1], 0.f));
                *(__half2*)(s + q * 2) = __float22half2_rn(v);
            }
        } else {
            #pragma unroll
            for (int q = 0; q < 16; q++) *(__half2*)(s + q * 2) = __float2half2_rn(0.f);
        }
    }
    __syncthreads();

    wmma::fragment<wmma::accumulator, 16, 16, 16, float> c[3];
    #pragma unroll
    for (int j = 0; j < 3; j++) wmma::fill_fragment(c[j], 0.f);

    #pragma unroll
    for (int k = 0; k < 64; k += 16) {
        wmma::fragment<wmma::matrix_a, 16, 16, 16, __half, wmma::row_major> a;
        wmma::load_matrix_sync(a, &Xh[(wid * 16) * X2S + k], X2S);
        #pragma unroll
        for (int j = 0; j < 3; j++) {
            wmma::fragment<wmma::matrix_b, 16, 16, 16, __half, wmma::row_major> b;
            wmma::load_matrix_sync(b, &Wh[k * W2S + j * 16], W2S);
            wmma::mma_sync(c[j], a, b, c[j]);
        }
    }
    __syncthreads();

    #pragma unroll
    for (int j = 0; j < 3; j++)
        wmma::store_matrix_sync(&Es[(wid * 16) * E2S + j * 16], c[j], E2S,
                                wmma::mem_row_major);
    __syncthreads();

    {   // epilogue
        int cb = (tid & 1) * 20;
        if (rowOK) {
            float s = g_dinv[grow];
            const float* ep = &Es[srow * E2S + cb];
            __half* d1 = &g_h2s [(long long)grow * CDIM + cb];
            __half* d2 = &g_agg2[(long long)grow * CDIM + cb];
            #pragma unroll
            for (int q = 0; q < 5; q++) {
                float4 v = *(const float4*)(ep + q * 4);
                __half2 h0 = __float22half2_rn(make_float2(v.x * s, v.y * s));
                __half2 h1 = __float22half2_rn(make_float2(v.z * s, v.w * s));
                uint2 pk = make_uint2(*(unsigned*)&h0, *(unsigned*)&h1);
                *(uint2*)(d1 + q * 4) = pk;
                *(uint2*)(d2 + q * 4) = pk;
            }
        }
    }
}

// -------- scatter2: agg2[dst] += h2s[src], 2 independent chains per thread ------
__device__ __forceinline__ void sc2_one(const int* __restrict__ ei, int E, long long idx) {
    int e = (int)(idx / 5);
    int c = (int)(idx % 5) * 8;
    int s = __ldcg(&ei[e]), d = __ldcg(&ei[E + e]);
    if ((unsigned)s >= (unsigned)N_NODES || (unsigned)d >= (unsigned)N_NODES) return;
    uint4 v = __ldcg((const uint4*)&g_h2s[(long long)s * CDIM + c]);
    __half* p = &g_agg2[(long long)d * CDIM + c];
    asm volatile("red.global.add.noftz.v4.f16x2 [%0], {%1, %2, %3, %4};"
                 :: "l"(p), "r"(v.x), "r"(v.y), "r"(v.z), "r"(v.w) : "memory");
}

__global__ void k_scatter2(const int* __restrict__ ei, int E) {
    long long total = (long long)E * 5;
    long long half = total >> 1;                  // total may be odd-safe below
    long long idx = (long long)blockIdx.x * blockDim.x + threadIdx.x;
    if (idx >= half + (total & 1)) return;
    if (idx < half) { sc2_one(ei, E, idx); sc2_one(ei, E, idx + half + (total & 1)); }
    else sc2_one(ei, E, idx);                     // middle element when total odd
}

// -------------------------------------- final: out = log_softmax(dinv*agg2 + b2)
__global__ void k_final(const float* __restrict__ b2, float* __restrict__ out) {
    int gtid = blockIdx.x * blockDim.x + threadIdx.x;
    int row  = gtid >> 5;
    int lane = threadIdx.x & 31;
    if (row >= N_NODES) return;
    const __half* rp = &g_agg2[(long long)row * CDIM];
    float s  = g_dinv[row];
    float a0 = s * __half2float(rp[lane]) + b2[lane];
    float a1 = (lane < 8) ? (s * __half2float(rp[32 + lane]) + b2[32 + lane]) : -3.4e38f;
    float m  = fmaxf(a0, a1);
    #pragma unroll
    for (int o = 16; o; o >>= 1) m = fmaxf(m, __shfl_xor_sync(0xFFFFFFFFu, m, o));
    float es = expf(a0 - m) + ((lane < 8) ? expf(a1 - m) : 0.f);
    #pragma unroll
    for (int o = 16; o; o >>= 1) es += __shfl_xor_sync(0xFFFFFFFFu, es, o);
    float l = m + logf(es);
    out[(long long)row * CDIM + lane] = a0 - l;
    if (lane < 8) out[(long long)row * CDIM + 32 + lane] = a1 - l;
}

// ---------------------------------------------------------------------------
extern "C" void kernel_launch(void* const* d_in, const int* in_sizes, int n_in,
                              void* d_out, int out_size) {
    const float* x  = (const float*)d_in[0];
    const int*   ei = (const int*)  d_in[1];
    const float* W1 = (const float*)d_in[2];
    const float* b1 = (const float*)d_in[3];
    const float* W2 = (const float*)d_in[4];
    const float* b2 = (const float*)d_in[5];
    float* out = (float*)d_out;
    const int E = in_sizes[1] / 2;

    static void* cnt_ptr = nullptr;
    if (cnt_ptr == nullptr) cudaGetSymbolAddress(&cnt_ptr, g_cnt);

    cudaMemsetAsync(cnt_ptr, 0, N_NODES * sizeof(int));
    k_count<<<(E + 255) / 256, 256>>>(ei, E);

    k_gemm1<<<(N_NODES + 127) / 128, 256>>>(x, W1);
    {
        long long half = ((long long)E * 8) >> 1;
        k_scatter1<<<(int)((half + 255) / 256), 256>>>(ei, E);
    }
    k_gemm2<<<(N_NODES + 127) / 128, 256>>>(W2, b1);
    {
        long long total = (long long)E * 5;
        long long work = (total >> 1) + (total & 1);
        k_scatter2<<<(int)((work + 255) / 256), 256>>>(ei, E);
    }
    k_final<<<(N_NODES * 32 + 255) / 256, 256>>>(b2, out);
}